// round 1
// baseline (speedup 1.0000x reference)
#include <cuda_runtime.h>
#include <math.h>

#define B_  4
#define T_  2048
#define E_  1024
#define H_  16
#define D_  64
#define F_  32
#define M_  (B_*T_)     // 8192
#define N3_ (3*E_)      // 3072

// Scratch (device globals; no allocation allowed)
__device__ float g_q[B_*H_*T_*D_];
__device__ float g_k[B_*H_*T_*D_];
__device__ float g_v[B_*H_*T_*D_];
__device__ float g_attn[M_*E_];

// ---------------------------------------------------------------------------
// GEMM-NT: C[m,n] = sum_k A[m,k] * W[n,k] + bias[n]
//   A: [M,K] row-major, W: [N,K] row-major.
//   mode 1: A = A_in (query), scatter C into g_q/g_k/g_v head-major layout
//   mode 2: A = g_attn, C = plain row-major output
// Tiles: BM=BN=128, BK=8, 256 threads, 8x8 per-thread micro-tile.
// ---------------------------------------------------------------------------
__global__ __launch_bounds__(256)
void gemm_kernel(const float* __restrict__ A_in,
                 const float* __restrict__ W,
                 const float* __restrict__ bias,
                 float* __restrict__ C,
                 int N, int K, int mode)
{
    const float* A = (mode == 2) ? g_attn : A_in;

    __shared__ float As[8][132];
    __shared__ float Bs[8][132];

    const int tid  = threadIdx.x;
    const int row0 = blockIdx.y * 128;
    const int col0 = blockIdx.x * 128;

    const int tr = (tid >> 4) << 3;   // 0..120 step 8 (output rows)
    const int tc = (tid & 15) << 3;   // 0..120 step 8 (output cols)

    const int lr = tid >> 1;          // 0..127 (load row)
    const int lc = (tid & 1) << 2;    // 0 or 4 (load col within k-tile)

    float acc[8][8];
#pragma unroll
    for (int i = 0; i < 8; i++)
#pragma unroll
        for (int j = 0; j < 8; j++) acc[i][j] = 0.f;

    const float* Aptr = A + (size_t)(row0 + lr) * K + lc;
    const float* Wptr = W + (size_t)(col0 + lr) * K + lc;

    for (int kt = 0; kt < K; kt += 8) {
        float4 av = *(const float4*)(Aptr + kt);
        float4 bv = *(const float4*)(Wptr + kt);
        As[lc + 0][lr] = av.x; As[lc + 1][lr] = av.y;
        As[lc + 2][lr] = av.z; As[lc + 3][lr] = av.w;
        Bs[lc + 0][lr] = bv.x; Bs[lc + 1][lr] = bv.y;
        Bs[lc + 2][lr] = bv.z; Bs[lc + 3][lr] = bv.w;
        __syncthreads();

#pragma unroll
        for (int kk = 0; kk < 8; kk++) {
            float ra[8], rb[8];
#pragma unroll
            for (int i = 0; i < 8; i++) ra[i] = As[kk][tr + i];
#pragma unroll
            for (int j = 0; j < 8; j++) rb[j] = Bs[kk][tc + j];
#pragma unroll
            for (int i = 0; i < 8; i++)
#pragma unroll
                for (int j = 0; j < 8; j++)
                    acc[i][j] += ra[i] * rb[j];
        }
        __syncthreads();
    }

    // Epilogue
    if (mode == 1) {
        // scatter into g_q / g_k / g_v with layout [B,H,T,D]
        // Each 128-wide col tile lies fully inside one of the 3 sections.
        const int n_any = col0;           // section is constant over the tile
        const int sec   = n_any >> 10;    // 0=q,1=k,2=v
        float* dst_base = (sec == 0) ? g_q : (sec == 1) ? g_k : g_v;
#pragma unroll
        for (int i = 0; i < 8; i++) {
            const int m = row0 + tr + i;
            const int b = m >> 11;        // m / 2048
            const int t = m & 2047;
#pragma unroll
            for (int j = 0; j < 8; j++) {
                const int n  = col0 + tc + j;
                const int nn = n & 1023;
                const int h  = nn >> 6;
                const int d  = nn & 63;
                dst_base[((size_t)(b * H_ + h) * T_ + t) * D_ + d] =
                    acc[i][j] + bias[n];
            }
        }
    } else {
#pragma unroll
        for (int i = 0; i < 8; i++) {
            const int m = row0 + tr + i;
#pragma unroll
            for (int j = 0; j < 8; j++) {
                const int n = col0 + tc + j;
                C[(size_t)m * N + n] = acc[i][j] + bias[n];
            }
        }
    }
}

// ---------------------------------------------------------------------------
// Rotary: one thread per (b,h,t,f). cos/sin shared between Q and K.
// ---------------------------------------------------------------------------
__global__ __launch_bounds__(256)
void rotary_kernel(const float* __restrict__ pos, const float* __restrict__ freqs)
{
    const int idx = blockIdx.x * blockDim.x + threadIdx.x;
    // idx bits: f[0:5) t[5:16) h[16:20) b[20:22)
    const int f = idx & 31;
    const int t = (idx >> 5) & 2047;
    const int h = (idx >> 16) & 15;
    const int b = idx >> 20;

    const float* p  = pos   + ((size_t)b * T_ + t) * 3;
    const float* fr = freqs + ((size_t)h * F_ + f) * 3;
    const float ang = p[0] * fr[0] + p[1] * fr[1] + p[2] * fr[2];
    float s, c;
    sincosf(ang, &s, &c);

    const size_t base = ((size_t)(b * H_ + h) * T_ + t) * D_ + 2 * f;
    const float q0 = g_q[base], q1 = g_q[base + 1];
    g_q[base]     = q0 * c - q1 * s;
    g_q[base + 1] = q0 * s + q1 * c;
    const float k0 = g_k[base], k1 = g_k[base + 1];
    g_k[base]     = k0 * c - k1 * s;
    g_k[base + 1] = k0 * s + k1 * c;
}

// ---------------------------------------------------------------------------
// Flash attention, fp32. Block = one (b,h) x 64-query tile; 256 threads.
// Smem tiles padded to stride 65 (conflict-free).
// ---------------------------------------------------------------------------
#define FA_SMEM_FLOATS (4 * 64 * 65 + 3 * 64)

__global__ __launch_bounds__(256)
void flash_kernel()
{
    extern __shared__ float sm[];
    float* Qs   = sm;                 // 64 x 65
    float* Ks   = sm + 4160;
    float* Vs   = sm + 8320;
    float* Ss   = sm + 12480;
    float* rowm = sm + 16640;         // 64
    float* rowl = rowm + 64;
    float* rowf = rowl + 64;

    const int tid = threadIdx.x;
    const int bh  = blockIdx.y;       // b*H + h
    const int q0  = blockIdx.x * 64;

    const float* Qg = g_q + ((size_t)bh * T_ + q0) * D_;
    const float* Kg = g_k + (size_t)bh * T_ * D_;
    const float* Vg = g_v + (size_t)bh * T_ * D_;

    for (int i = tid; i < 4096; i += 256) {
        const int r = i >> 6, c = i & 63;
        Qs[r * 65 + c] = Qg[i];
    }
    if (tid < 64) { rowm[tid] = -INFINITY; rowl[tid] = 0.f; }

    const int sr = (tid >> 4) << 2;   // 4 output rows
    const int sc = (tid & 15) << 2;   // 4 output cols

    float o[4][4];
#pragma unroll
    for (int i = 0; i < 4; i++)
#pragma unroll
        for (int j = 0; j < 4; j++) o[i][j] = 0.f;

    for (int j0 = 0; j0 < T_; j0 += 64) {
        __syncthreads();  // protect Ks/Vs/Ss reuse; also fences Q load (iter 0)
        for (int i = tid; i < 4096; i += 256) {
            const int r = i >> 6, c = i & 63;
            Ks[r * 65 + c] = Kg[(size_t)j0 * 64 + i];
            Vs[r * 65 + c] = Vg[(size_t)j0 * 64 + i];
        }
        __syncthreads();

        // S = Q K^T * scale (4x4 per thread)
        float s[4][4];
#pragma unroll
        for (int i = 0; i < 4; i++)
#pragma unroll
            for (int j = 0; j < 4; j++) s[i][j] = 0.f;

#pragma unroll 8
        for (int d = 0; d < 64; d++) {
            float qa[4], kb[4];
#pragma unroll
            for (int i = 0; i < 4; i++) qa[i] = Qs[(sr + i) * 65 + d];
#pragma unroll
            for (int j = 0; j < 4; j++) kb[j] = Ks[(sc + j) * 65 + d];
#pragma unroll
            for (int i = 0; i < 4; i++)
#pragma unroll
                for (int j = 0; j < 4; j++)
                    s[i][j] += qa[i] * kb[j];
        }
#pragma unroll
        for (int i = 0; i < 4; i++)
#pragma unroll
            for (int j = 0; j < 4; j++)
                Ss[(sr + i) * 65 + sc + j] = s[i][j] * 0.125f;
        __syncthreads();

        // online softmax, one thread per row
        if (tid < 64) {
            const int r = tid;
            const float mo = rowm[r];
            float mx = mo;
#pragma unroll 8
            for (int c = 0; c < 64; c++) mx = fmaxf(mx, Ss[r * 65 + c]);
            float sum = 0.f;
#pragma unroll 8
            for (int c = 0; c < 64; c++) {
                const float p = __expf(Ss[r * 65 + c] - mx);
                Ss[r * 65 + c] = p;
                sum += p;
            }
            const float fct = __expf(mo - mx);
            rowl[r] = rowl[r] * fct + sum;
            rowm[r] = mx;
            rowf[r] = fct;
        }
        __syncthreads();

        // rescale O, accumulate P*V
        float fi[4];
#pragma unroll
        for (int i = 0; i < 4; i++) fi[i] = rowf[sr + i];
#pragma unroll
        for (int i = 0; i < 4; i++)
#pragma unroll
            for (int j = 0; j < 4; j++) o[i][j] *= fi[i];

#pragma unroll 8
        for (int c = 0; c < 64; c++) {
            float vb[4], pa[4];
#pragma unroll
            for (int j = 0; j < 4; j++) vb[j] = Vs[c * 65 + sc + j];
#pragma unroll
            for (int i = 0; i < 4; i++) pa[i] = Ss[(sr + i) * 65 + c];
#pragma unroll
            for (int i = 0; i < 4; i++)
#pragma unroll
                for (int j = 0; j < 4; j++)
                    o[i][j] += pa[i] * vb[j];
        }
    }

    // finalize: divide by l, write attn output in [B,T, h*D+d] layout
    float li[4];
#pragma unroll
    for (int i = 0; i < 4; i++) li[i] = 1.f / rowl[sr + i];

    const int b = bh >> 4;
    const int h = bh & 15;
#pragma unroll
    for (int i = 0; i < 4; i++) {
        const int t = q0 + sr + i;
        float* dst = g_attn + ((size_t)(b * T_ + t)) * E_ + h * D_ + sc;
#pragma unroll
        for (int j = 0; j < 4; j++) dst[j] = o[i][j] * li[i];
    }
}

// ---------------------------------------------------------------------------
extern "C" void kernel_launch(void* const* d_in, const int* in_sizes, int n_in,
                              void* d_out, int out_size)
{
    const float* query     = (const float*)d_in[0];
    const float* positions = (const float*)d_in[1];
    const float* in_w      = (const float*)d_in[2];
    const float* in_b      = (const float*)d_in[3];
    const float* out_w     = (const float*)d_in[4];
    const float* out_b     = (const float*)d_in[5];
    const float* freqs     = (const float*)d_in[6];
    float* out = (float*)d_out;

    cudaFuncSetAttribute(flash_kernel,
                         cudaFuncAttributeMaxDynamicSharedMemorySize,
                         FA_SMEM_FLOATS * (int)sizeof(float));

    // 1) QKV projection, scattered head-major
    gemm_kernel<<<dim3(N3_ / 128, M_ / 128), 256>>>(query, in_w, in_b,
                                                    nullptr, N3_, E_, 1);
    // 2) rotary on Q and K
    rotary_kernel<<<(B_ * H_ * T_ * F_) / 256, 256>>>(positions, freqs);
    // 3) attention
    flash_kernel<<<dim3(T_ / 64, B_ * H_), 256,
                   FA_SMEM_FLOATS * (int)sizeof(float)>>>();
    // 4) output projection
    gemm_kernel<<<dim3(E_ / 128, M_ / 128), 256>>>(nullptr, out_w, out_b,
                                                   out, E_, E_, 2);
}